// round 3
// baseline (speedup 1.0000x reference)
#include <cuda_runtime.h>
#include <math.h>

#define Bn 128
#define Tn 256
#define Hn 128
#define Cn 10
#define Gn 512   // 4*H

// ---------------- scratch (static device memory; no allocs) ----------------
__device__ float g_H[Bn * Tn * Hn];   // hidden states h_t, layout [b][t][h]  (16 MB)
__device__ float g_a[Bn * Tn];        // a_t[b]  = sum_h tanh(h_t) * w_t[0:H]
__device__ float g_s[Bn * Tn];        // s from h_t (used as slot t+1 score part)
__device__ float g_p[Bn * Tn * 12];   // p_t[b,c] = h_t . fc_W[c,:], padded to 12

// ============================================================================
// Phase 1: per-batch LSTM recurrence.
// 128 CTAs (one per batch row), 1024 threads = (gate g in [0,512)) x (k-half).
// Each thread computes a 64-long partial dot for its gate:
//   32 weights register-resident, 32 streamed from smem ([k][g] layout,
//   coalesced & bank-conflict-free). h broadcast from smem via float4.
// ============================================================================
__global__ __launch_bounds__(1024, 1) void lstm_rec(
    const float* __restrict__ x,
    const float* __restrict__ W_ih,
    const float* __restrict__ W_hh,
    const float* __restrict__ b_ih,
    const float* __restrict__ b_hh)
{
    extern __shared__ float sm[];
    float* Wsm     = sm;                 // [64][512] smem-resident weights (128 KB)
    float* red     = Wsm + 64 * 512;     // [1024] partial sums
    float* h_sh    = red + 1024;         // [128]
    float* c_sh    = h_sh + 128;         // [128]
    float* x_sh    = c_sh + 128;         // [256]
    float* wih_sh  = x_sh + 256;         // [512]
    float* bias_sh = wih_sh + 512;       // [512]

    const int b      = blockIdx.x;
    const int tid    = threadIdx.x;
    const int g      = tid & 511;
    const int half   = tid >> 9;         // 0: k in [0,64), 1: k in [64,128)
    const int kstart = half * 64;

    // ---- load weights: 32 in registers, 32 into smem ----
    float wr[32];
    const float* wrow = W_hh + g * Hn + kstart;
#pragma unroll
    for (int i = 0; i < 32; i++) wr[i] = wrow[i];
#pragma unroll
    for (int i = 0; i < 32; i++) Wsm[(half * 32 + i) * 512 + g] = wrow[32 + i];

    if (tid < 512) {
        wih_sh[tid]  = W_ih[tid];
        bias_sh[tid] = b_ih[tid] + b_hh[tid];
    }
    if (tid < 128) { h_sh[tid] = 0.f; c_sh[tid] = 0.f; }
    if (tid < 256) x_sh[tid] = x[b * Tn + tid];
    __syncthreads();

    float* Hout = g_H + b * Tn * Hn;
    const float* wsb = Wsm + half * 32 * 512 + g;

    for (int t = 0; t < Tn; t++) {
        // ---- partial dot: gates[g] partial over this thread's 64 k values ----
        float acc = 0.f;
        const float4* h4a = (const float4*)(h_sh + kstart);
        const float4* h4b = (const float4*)(h_sh + kstart + 32);
#pragma unroll
        for (int q = 0; q < 8; q++) {
            float4 hv = h4a[q];
            acc = fmaf(wr[4 * q + 0], hv.x, acc);
            acc = fmaf(wr[4 * q + 1], hv.y, acc);
            acc = fmaf(wr[4 * q + 2], hv.z, acc);
            acc = fmaf(wr[4 * q + 3], hv.w, acc);
        }
#pragma unroll
        for (int q = 0; q < 8; q++) {
            float4 hv = h4b[q];
            acc = fmaf(wsb[(4 * q + 0) * 512], hv.x, acc);
            acc = fmaf(wsb[(4 * q + 1) * 512], hv.y, acc);
            acc = fmaf(wsb[(4 * q + 2) * 512], hv.z, acc);
            acc = fmaf(wsb[(4 * q + 3) * 512], hv.w, acc);
        }
        red[tid] = acc;
        __syncthreads();

        // ---- cell update by 128 threads (j = hidden index) ----
        if (tid < 128) {
            const int j = tid;
            const float xt = x_sh[t];
            float gi = red[j]       + red[j + 512] + xt * wih_sh[j]       + bias_sh[j];
            float gf = red[j + 128] + red[j + 640] + xt * wih_sh[j + 128] + bias_sh[j + 128];
            float gg = red[j + 256] + red[j + 768] + xt * wih_sh[j + 256] + bias_sh[j + 256];
            float go = red[j + 384] + red[j + 896] + xt * wih_sh[j + 384] + bias_sh[j + 384];
            float sf = 1.f / (1.f + expf(-gf));
            float si = 1.f / (1.f + expf(-gi));
            float so = 1.f / (1.f + expf(-go));
            float c  = sf * c_sh[j] + si * tanhf(gg);
            float h  = so * tanhf(c);
            c_sh[j] = c;
            h_sh[j] = h;
            Hout[t * Hn + j] = h;
        }
        __syncthreads();
    }
}

// ============================================================================
// Phase 2: per-state scalars a, s and projection p = h . fc_W^T (C=10).
// One warp per (b,t). 12 interleaved butterfly reductions.
// ============================================================================
__global__ __launch_bounds__(256) void lstm_post(
    const float* __restrict__ w_t,
    const float* __restrict__ fc_W)
{
    const int wid  = blockIdx.x * 8 + (threadIdx.x >> 5);
    const int lane = threadIdx.x & 31;
    if (wid >= Bn * Tn) return;

    const float* hrow = g_H + wid * Hn;
    float h0 = hrow[lane], h1 = hrow[lane + 32], h2 = hrow[lane + 64], h3 = hrow[lane + 96];
    float t0 = tanhf(h0), t1 = tanhf(h1), t2 = tanhf(h2), t3 = tanhf(h3);

    float v[12];
    // a : tanh(h) . w_t[0:128]
    v[0] = t0 * w_t[lane] + t1 * w_t[lane + 32] + t2 * w_t[lane + 64] + t3 * w_t[lane + 96];
    // s : tanh(h) . w_t[128:256]
    v[1] = t0 * w_t[128 + lane] + t1 * w_t[160 + lane] + t2 * w_t[192 + lane] + t3 * w_t[224 + lane];
    // p_c : h . fc_W[c,:]
#pragma unroll
    for (int c = 0; c < Cn; c++) {
        const float* fw = fc_W + c * Hn;
        v[2 + c] = h0 * fw[lane] + h1 * fw[lane + 32] + h2 * fw[lane + 64] + h3 * fw[lane + 96];
    }
#pragma unroll
    for (int off = 16; off > 0; off >>= 1) {
#pragma unroll
        for (int i = 0; i < 12; i++)
            v[i] += __shfl_xor_sync(0xffffffffu, v[i], off);
    }
    if (lane == 0) {
        g_a[wid] = v[0];
        g_s[wid] = v[1];
        float* pr = g_p + wid * 12;
#pragma unroll
        for (int c = 0; c < Cn; c++) pr[c] = v[2 + c];
        pr[10] = 0.f; pr[11] = 0.f;
    }
}

// ============================================================================
// Phase 3: out[b,t,:] = p_t + fc_b + sum_{j=1..t} sigmoid(a_t + s_{j-1}) * p_{j-1}
// One block per batch, thread = t. Uniform j loop -> broadcast smem reads.
// ============================================================================
__global__ __launch_bounds__(256) void lstm_attn(
    const float* __restrict__ fc_b,
    float* __restrict__ out)
{
    __shared__ float sA[256];
    __shared__ float sS[256];
    __shared__ float sP[256 * 12];

    const int b = blockIdx.x, tid = threadIdx.x;
    sA[tid] = g_a[b * Tn + tid];
    sS[tid] = g_s[b * Tn + tid];
    const float4* gp4 = (const float4*)(g_p + b * Tn * 12);
    float4* sP4 = (float4*)sP;
#pragma unroll
    for (int i = 0; i < 3; i++) sP4[tid + i * 256] = gp4[tid + i * 256];
    __syncthreads();

    const int t = tid;
    const float at = sA[t];
    const float4* myp = (const float4*)(sP + t * 12);
    float4 a0 = myp[0], a1 = myp[1], a2 = myp[2];
    a0.x += fc_b[0]; a0.y += fc_b[1]; a0.z += fc_b[2]; a0.w += fc_b[3];
    a1.x += fc_b[4]; a1.y += fc_b[5]; a1.z += fc_b[6]; a1.w += fc_b[7];
    a2.x += fc_b[8]; a2.y += fc_b[9];

    const int jmax = t | 31;   // warp-uniform upper bound
    for (int j = 1; j <= jmax; j++) {
        float w = 1.f / (1.f + __expf(-(at + sS[j - 1])));
        w = (j <= t) ? w : 0.f;
        const float4* q = (const float4*)(sP + (j - 1) * 12);
        float4 q0 = q[0], q1 = q[1], q2 = q[2];
        a0.x = fmaf(w, q0.x, a0.x); a0.y = fmaf(w, q0.y, a0.y);
        a0.z = fmaf(w, q0.z, a0.z); a0.w = fmaf(w, q0.w, a0.w);
        a1.x = fmaf(w, q1.x, a1.x); a1.y = fmaf(w, q1.y, a1.y);
        a1.z = fmaf(w, q1.z, a1.z); a1.w = fmaf(w, q1.w, a1.w);
        a2.x = fmaf(w, q2.x, a2.x); a2.y = fmaf(w, q2.y, a2.y);
    }
    float* o = out + (b * Tn + t) * Cn;
    o[0] = a0.x; o[1] = a0.y; o[2] = a0.z; o[3] = a0.w;
    o[4] = a1.x; o[5] = a1.y; o[6] = a1.z; o[7] = a1.w;
    o[8] = a2.x; o[9] = a2.y;
}

// ============================================================================
extern "C" void kernel_launch(void* const* d_in, const int* in_sizes, int n_in,
                              void* d_out, int out_size)
{
    const float* x    = (const float*)d_in[0];
    const float* W_ih = (const float*)d_in[1];
    const float* W_hh = (const float*)d_in[2];
    const float* b_ih = (const float*)d_in[3];
    const float* b_hh = (const float*)d_in[4];
    const float* w_t  = (const float*)d_in[5];
    const float* fc_W = (const float*)d_in[6];
    const float* fc_b = (const float*)d_in[7];
    float* out = (float*)d_out;

    const size_t smem = (size_t)(64 * 512 + 1024 + 128 + 128 + 256 + 512 + 512) * sizeof(float);
    // Idempotent; also executed (successfully) on the pre-capture correctness call.
    cudaFuncSetAttribute(lstm_rec, cudaFuncAttributeMaxDynamicSharedMemorySize, (int)smem);

    lstm_rec<<<Bn, 1024, smem>>>(x, W_ih, W_hh, b_ih, b_hh);
    lstm_post<<<(Bn * Tn) / 8, 256>>>(w_t, fc_W);
    lstm_attn<<<Bn, 256>>>(fc_b, out);
}

// round 4
// speedup vs baseline: 1.5332x; 1.5332x over previous
#include <cuda_runtime.h>
#include <cuda_fp16.h>
#include <math.h>

#define Bn 128
#define Tn 256
#define Hn 128
#define Cn 10

// ---------------- scratch (static device memory; no allocs) ----------------
__device__ float g_H[Bn * Tn * Hn];   // hidden states h_t, [b][t][h] (16 MB)
__device__ float g_a[Bn * Tn];        // a_t[b] = tanh(h_t) . w_t[0:H]
__device__ float g_s[Bn * Tn];        // s_t[b] = tanh(h_t) . w_t[H:2H]
__device__ float g_p[Bn * Tn * 12];   // p_t[b,c] = h_t . fc_W[c,:], padded to 12

// ============================================================================
// Phase 1: per-batch LSTM recurrence. 128 CTAs x 1024 threads.
// All of W_hh lives in registers as fp16 (32 half2/thread). h kept in smem as
// fp16 (ping-pong). Warp w owns hidden units j in {4w..4w+3}; lane layout:
//   l = (half<<4) | (gate<<2) | jj,  gate row g = gate*128 + 4w + jj,
//   k-slice = [64*half, 64*half+64).
// One __syncthreads per step; gate combine + cell update are warp-local.
// ============================================================================
__global__ __launch_bounds__(1024, 1) void lstm_rec(
    const float* __restrict__ x,
    const float* __restrict__ W_ih,
    const float* __restrict__ W_hh,
    const float* __restrict__ b_ih,
    const float* __restrict__ b_hh)
{
    __shared__ __align__(16) __half h16[2][Hn];
    __shared__ float x_sh[Tn];

    const int b    = blockIdx.x;
    const int tid  = threadIdx.x;
    const int w    = tid >> 5;
    const int l    = tid & 31;
    const int jj   = l & 3;
    const int gt   = (l >> 2) & 3;
    const int half = l >> 4;
    const int g    = gt * Hn + (w << 2) + jj;     // gate row in W_hh
    const int k0   = half * 64;                   // k-slice start
    const int jown = (w << 2) + jj;               // owned hidden unit

    // ---- pack this thread's 64 weights into 32 half2 registers ----
    half2 w2[32];
    const float* wrow = W_hh + g * Hn + k0;
#pragma unroll
    for (int i = 0; i < 32; i++)
        w2[i] = __floats2half2_rn(wrow[2 * i], wrow[2 * i + 1]);

    const float wih_r  = W_ih[g];
    const float bias_r = b_ih[g] + b_hh[g];

    if (tid < Tn) x_sh[tid] = x[b * Tn + tid];
    if (tid < Hn) {
        h16[0][tid] = __float2half(0.f);
        h16[1][tid] = __float2half(0.f);
    }
    __syncthreads();

    float c = 0.f;
    float* Hout = g_H + b * Tn * Hn;

    for (int t = 0; t < Tn; t++) {
        // ---- 64-term partial dot in fp16 (two independent half2 chains) ----
        const uint4* hp = (const uint4*)(&h16[t & 1][k0]);
        half2 a0 = __floats2half2_rn(0.f, 0.f);
        half2 a1 = a0;
#pragma unroll
        for (int q = 0; q < 8; q++) {
            uint4 hv = hp[q];
            a0 = __hfma2(w2[4 * q + 0], *(const half2*)&hv.x, a0);
            a1 = __hfma2(w2[4 * q + 1], *(const half2*)&hv.y, a1);
            a0 = __hfma2(w2[4 * q + 2], *(const half2*)&hv.z, a0);
            a1 = __hfma2(w2[4 * q + 3], *(const half2*)&hv.w, a1);
        }
        float2 f0 = __half22float2(a0);
        float2 f1 = __half22float2(a1);
        float sum = (f0.x + f0.y) + (f1.x + f1.y);
        if (l < 16) sum += fmaf(x_sh[t], wih_r, bias_r);  // add bias/input once
        sum += __shfl_xor_sync(0xffffffffu, sum, 16);     // combine k-halves

        // ---- gather all 4 gates for my jj (warp-local) ----
        float gi = __shfl_sync(0xffffffffu, sum, jj);
        float gf = __shfl_sync(0xffffffffu, sum, jj | 4);
        float gg = __shfl_sync(0xffffffffu, sum, jj | 8);
        float go = __shfl_sync(0xffffffffu, sum, jj | 12);

        // ---- cell update (redundant across lanes with same jj) ----
        float ei = __expf(-gi);
        float ef = __expf(-gf);
        float eg = __expf(-2.f * gg);
        float eo = __expf(-go);
        float sf  = __fdividef(1.f, 1.f + ef);                          // sigmoid(f)
        float itg = __fdividef(1.f - eg, (1.f + ei) * (1.f + eg));      // sig(i)*tanh(g)
        c = fmaf(sf, c, itg);
        c = fminf(fmaxf(c, -30.f), 30.f);                               // NaN guard
        float ec = __expf(-2.f * c);
        float h  = __fdividef(1.f - ec, (1.f + eo) * (1.f + ec));       // sig(o)*tanh(c)

        if (l < 4)      h16[(t + 1) & 1][jown] = __float2half_rn(h);
        else if (l < 8) Hout[t * Hn + jown] = h;
        __syncthreads();
    }
}

// ============================================================================
// Phase 2: per-state scalars a, s and projection p = h . fc_W^T (C=10).
// One warp per (b,t). 12 interleaved butterfly reductions.
// ============================================================================
__global__ __launch_bounds__(256) void lstm_post(
    const float* __restrict__ w_t,
    const float* __restrict__ fc_W)
{
    const int wid  = blockIdx.x * 8 + (threadIdx.x >> 5);
    const int lane = threadIdx.x & 31;
    if (wid >= Bn * Tn) return;

    const float* hrow = g_H + wid * Hn;
    float h0 = hrow[lane], h1 = hrow[lane + 32], h2 = hrow[lane + 64], h3 = hrow[lane + 96];
    float t0 = tanhf(h0), t1 = tanhf(h1), t2 = tanhf(h2), t3 = tanhf(h3);

    float v[12];
    v[0] = t0 * w_t[lane] + t1 * w_t[lane + 32] + t2 * w_t[lane + 64] + t3 * w_t[lane + 96];
    v[1] = t0 * w_t[128 + lane] + t1 * w_t[160 + lane] + t2 * w_t[192 + lane] + t3 * w_t[224 + lane];
#pragma unroll
    for (int c = 0; c < Cn; c++) {
        const float* fw = fc_W + c * Hn;
        v[2 + c] = h0 * fw[lane] + h1 * fw[lane + 32] + h2 * fw[lane + 64] + h3 * fw[lane + 96];
    }
#pragma unroll
    for (int off = 16; off > 0; off >>= 1) {
#pragma unroll
        for (int i = 0; i < 12; i++)
            v[i] += __shfl_xor_sync(0xffffffffu, v[i], off);
    }
    if (lane == 0) {
        g_a[wid] = v[0];
        g_s[wid] = v[1];
        float* pr = g_p + wid * 12;
#pragma unroll
        for (int c = 0; c < Cn; c++) pr[c] = v[2 + c];
        pr[10] = 0.f; pr[11] = 0.f;
    }
}

// ============================================================================
// Phase 3: out[b,t,:] = p_t + fc_b + sum_{j=1..t} sigmoid(a_t + s_{j-1}) * p_{j-1}
// One block per batch, thread = t.
// ============================================================================
__global__ __launch_bounds__(256) void lstm_attn(
    const float* __restrict__ fc_b,
    float* __restrict__ out)
{
    __shared__ float sA[256];
    __shared__ float sS[256];
    __shared__ float sP[256 * 12];

    const int b = blockIdx.x, tid = threadIdx.x;
    sA[tid] = g_a[b * Tn + tid];
    sS[tid] = g_s[b * Tn + tid];
    const float4* gp4 = (const float4*)(g_p + b * Tn * 12);
    float4* sP4 = (float4*)sP;
#pragma unroll
    for (int i = 0; i < 3; i++) sP4[tid + i * 256] = gp4[tid + i * 256];
    __syncthreads();

    const int t = tid;
    const float at = sA[t];
    const float4* myp = (const float4*)(sP + t * 12);
    float4 a0 = myp[0], a1 = myp[1], a2 = myp[2];
    a0.x += fc_b[0]; a0.y += fc_b[1]; a0.z += fc_b[2]; a0.w += fc_b[3];
    a1.x += fc_b[4]; a1.y += fc_b[5]; a1.z += fc_b[6]; a1.w += fc_b[7];
    a2.x += fc_b[8]; a2.y += fc_b[9];

    const int jmax = t | 31;   // warp-uniform upper bound
    for (int j = 1; j <= jmax; j++) {
        float wgt = 1.f / (1.f + __expf(-(at + sS[j - 1])));
        wgt = (j <= t) ? wgt : 0.f;
        const float4* q = (const float4*)(sP + (j - 1) * 12);
        float4 q0 = q[0], q1 = q[1], q2 = q[2];
        a0.x = fmaf(wgt, q0.x, a0.x); a0.y = fmaf(wgt, q0.y, a0.y);
        a0.z = fmaf(wgt, q0.z, a0.z); a0.w = fmaf(wgt, q0.w, a0.w);
        a1.x = fmaf(wgt, q1.x, a1.x); a1.y = fmaf(wgt, q1.y, a1.y);
        a1.z = fmaf(wgt, q1.z, a1.z); a1.w = fmaf(wgt, q1.w, a1.w);
        a2.x = fmaf(wgt, q2.x, a2.x); a2.y = fmaf(wgt, q2.y, a2.y);
    }
    float* o = out + (b * Tn + t) * Cn;
    o[0] = a0.x; o[1] = a0.y; o[2] = a0.z; o[3] = a0.w;
    o[4] = a1.x; o[5] = a1.y; o[6] = a1.z; o[7] = a1.w;
    o[8] = a2.x; o[9] = a2.y;
}

// ============================================================================
extern "C" void kernel_launch(void* const* d_in, const int* in_sizes, int n_in,
                              void* d_out, int out_size)
{
    const float* x    = (const float*)d_in[0];
    const float* W_ih = (const float*)d_in[1];
    const float* W_hh = (const float*)d_in[2];
    const float* b_ih = (const float*)d_in[3];
    const float* b_hh = (const float*)d_in[4];
    const float* w_t  = (const float*)d_in[5];
    const float* fc_W = (const float*)d_in[6];
    const float* fc_b = (const float*)d_in[7];
    float* out = (float*)d_out;

    lstm_rec<<<Bn, 1024>>>(x, W_ih, W_hh, b_ih, b_hh);
    lstm_post<<<(Bn * Tn) / 8, 256>>>(w_t, fc_W);
    lstm_attn<<<Bn, 256>>>(fc_b, out);
}

// round 5
// speedup vs baseline: 2.2106x; 1.4418x over previous
#include <cuda_runtime.h>
#include <cuda_fp16.h>
#include <math.h>

#define Bn 128
#define Tn 256
#define Hn 128
#define Cn 10

__device__ __forceinline__ float tanh_fast(float v) {
    float y;
    asm("tanh.approx.f32 %0, %1;" : "=f"(y) : "f"(v));
    return y;
}

// ---------------------------------------------------------------------------
// One fused kernel. CTA b handles batch row b end-to-end:
//   Phase 1: 256-step LSTM recurrence (W_hh register-resident fp16).
//   Phase 2: per-t scalars a,s and projection p = h.fc_W^T (warp per 8 rows).
//   Phase 3: attention-weighted sum of p over history + output.
// Everything stays in shared memory; no global scratch.
//
// Phase-1 lane layout within each warp: l = half*16 + gate*4 + jj.
//   gate row g = gate*128 + 4w + jj ; k-slice [64*half, 64*half+64).
// After xor16 combine, gate-lane groups hold: gt0=sig(i), gt1=sig(f),
// gt2=tanh(g), gt3=sig(o) (one MUFU.TANH for all). xor8 forms sig(i)*tanh(g),
// xor12 routes sig(f)/sig(o)/itg, xor4 broadcasts tanh(c). One bar per step.
// ---------------------------------------------------------------------------
__global__ __launch_bounds__(1024, 1) void lstm_fused(
    const float* __restrict__ x,
    const float* __restrict__ W_ih,
    const float* __restrict__ W_hh,
    const float* __restrict__ b_ih,
    const float* __restrict__ b_hh,
    const float* __restrict__ w_t,
    const float* __restrict__ fc_W,
    const float* __restrict__ fc_b,
    float* __restrict__ out)
{
    extern __shared__ __align__(16) char smraw[];
    float*  Hf   = (float*)smraw;                    // [256][128] f32, 131072 B
    float*  sP   = (float*)(smraw + 131072);         // [256][12]       12288 B
    float*  sA   = (float*)(smraw + 143360);         // [256]            1024 B
    float*  sS   = (float*)(smraw + 144384);         // [256]            1024 B
    float*  x_sh = (float*)(smraw + 145408);         // [256]            1024 B
    __half* h16  = (__half*)(smraw + 146432);        // 2 x [128] fp16    512 B

    const int b    = blockIdx.x;
    const int tid  = threadIdx.x;
    const int w    = tid >> 5;
    const int l    = tid & 31;
    const int jj   = l & 3;
    const int gt   = (l >> 2) & 3;
    const int g    = gt * Hn + (w << 2) + jj;     // gate row
    const int k0   = (l >> 4) * 64;               // k-slice start
    const int jown = (w << 2) + jj;               // owned hidden unit

    // ---- W_hh -> 32 half2 registers per thread ----
    half2 w2[32];
    {
        const float* wrow = W_hh + g * Hn + k0;
#pragma unroll
        for (int i = 0; i < 32; i++)
            w2[i] = __floats2half2_rn(wrow[2 * i], wrow[2 * i + 1]);
    }
    const float wih_r  = W_ih[g];
    const float bias_r = b_ih[g] + b_hh[g];

    if (tid < Tn) x_sh[tid] = x[b * Tn + tid];
    if (tid < Hn) { h16[tid] = __float2half(0.f); h16[Hn + tid] = __float2half(0.f); }
    __syncthreads();

    // ================= Phase 1: recurrence =================
    float c = 0.f;
#pragma unroll 2
    for (int t = 0; t < Tn; t++) {
        const uint4* hp = (const uint4*)(h16 + (t & 1) * Hn + k0);
        half2 a0 = __float2half2_rn(0.f), a1 = a0;
#pragma unroll
        for (int q = 0; q < 8; q++) {
            uint4 hv = hp[q];
            a0 = __hfma2(w2[4 * q + 0], *(const half2*)&hv.x, a0);
            a1 = __hfma2(w2[4 * q + 1], *(const half2*)&hv.y, a1);
            a0 = __hfma2(w2[4 * q + 2], *(const half2*)&hv.z, a0);
            a1 = __hfma2(w2[4 * q + 3], *(const half2*)&hv.w, a1);
        }
        float2 ff = __half22float2(__hadd2(a0, a1));
        float sum = ff.x + ff.y;
        if (l < 16) sum += fmaf(x_sh[t], wih_r, bias_r);   // add once per gate
        sum += __shfl_xor_sync(0xffffffffu, sum, 16);      // combine k-halves

        // one MUFU.TANH gives all four activations across gate-lane groups
        const bool isg = (gt == 2);
        float tv  = tanh_fast(isg ? sum : 0.5f * sum);
        float act = isg ? tv : fmaf(0.5f, tv, 0.5f);       // gt0:si gt1:sf gt2:tg gt3:so

        float p8 = __shfl_xor_sync(0xffffffffu, act, 8);   // gt0<->gt2, gt1<->gt3
        float vC = ((gt & 1) == 0) ? act * p8 : act;       // gt0/gt2: itg; gt1:sf; gt3:so
        float r  = __shfl_xor_sync(0xffffffffu, vC, 12);   // gt0<-so gt1<-itg gt2<-sf gt3<-itg

        float sfv  = (gt == 1) ? vC : r;
        float itgv = (gt == 1) ? r  : vC;
        c = fmaf(sfv, c, itgv);                            // valid on gt1, gt2 (identical)
        float tc  = tanh_fast(c);
        float tcx = __shfl_xor_sync(0xffffffffu, tc, 4);   // gt0<-gt1, gt3<-gt2
        float so  = (gt == 0) ? r : act;
        float h   = so * tcx;                              // valid on gt0, gt3

        if (l < 4)              h16[((t + 1) & 1) * Hn + jown] = __float2half_rn(h);
        else if ((l >> 2) == 3) Hf[t * Hn + jown] = h;     // lanes 12..15
        __syncthreads();
    }

    // ================= Phase 2: a, s, p per (t) =================
    // warp w handles rows t = 8w .. 8w+7; accurate tanhf here (cheap, off hot loop)
    for (int i = 0; i < 8; i++) {
        const int t = (w << 3) + i;
        const float* hrow = Hf + t * Hn;
        float h0 = hrow[l], h1 = hrow[l + 32], h2 = hrow[l + 64], h3 = hrow[l + 96];
        float t0 = tanhf(h0), t1 = tanhf(h1), t2 = tanhf(h2), t3 = tanhf(h3);

        float v[12];
        v[0] = t0 * w_t[l]       + t1 * w_t[l + 32]  + t2 * w_t[l + 64]  + t3 * w_t[l + 96];
        v[1] = t0 * w_t[128 + l] + t1 * w_t[160 + l] + t2 * w_t[192 + l] + t3 * w_t[224 + l];
#pragma unroll
        for (int cc = 0; cc < Cn; cc++) {
            const float* fw = fc_W + cc * Hn;
            v[2 + cc] = h0 * fw[l] + h1 * fw[l + 32] + h2 * fw[l + 64] + h3 * fw[l + 96];
        }
#pragma unroll
        for (int off = 16; off > 0; off >>= 1)
#pragma unroll
            for (int k = 0; k < 12; k++)
                v[k] += __shfl_xor_sync(0xffffffffu, v[k], off);
        if (l == 0) {
            sA[t] = v[0];
            sS[t] = v[1];
            float* pr = sP + t * 12;
#pragma unroll
            for (int cc = 0; cc < Cn; cc++) pr[cc] = v[2 + cc];
            pr[10] = 0.f; pr[11] = 0.f;
        }
    }
    __syncthreads();

    // ================= Phase 3: attention + output =================
    // thread = (t, part): partial sum over j-1 ≡ part (mod 4), combine via shfl.
    {
        const int t    = tid >> 2;
        const int part = tid & 3;
        const float at = sA[t];
        float acc[10];
#pragma unroll
        for (int i = 0; i < 10; i++) acc[i] = 0.f;

        const int jmaxW = (w << 3) + 7;            // warp-uniform bound (max t in warp)
        for (int jm1 = part; jm1 < jmaxW; jm1 += 4) {
            float wgt = __fdividef(1.f, 1.f + __expf(-(at + sS[jm1])));
            wgt = (jm1 < t) ? wgt : 0.f;
            const float4* q = (const float4*)(sP + jm1 * 12);
            float4 q0 = q[0], q1 = q[1], q2 = q[2];
            acc[0] = fmaf(wgt, q0.x, acc[0]); acc[1] = fmaf(wgt, q0.y, acc[1]);
            acc[2] = fmaf(wgt, q0.z, acc[2]); acc[3] = fmaf(wgt, q0.w, acc[3]);
            acc[4] = fmaf(wgt, q1.x, acc[4]); acc[5] = fmaf(wgt, q1.y, acc[5]);
            acc[6] = fmaf(wgt, q1.z, acc[6]); acc[7] = fmaf(wgt, q1.w, acc[7]);
            acc[8] = fmaf(wgt, q2.x, acc[8]); acc[9] = fmaf(wgt, q2.y, acc[9]);
        }
#pragma unroll
        for (int off = 1; off <= 2; off <<= 1)
#pragma unroll
            for (int i = 0; i < 10; i++)
                acc[i] += __shfl_xor_sync(0xffffffffu, acc[i], off);

        if (part == 0) {
            float* o = out + (b * Tn + t) * Cn;
            const float* pr = sP + t * 12;
#pragma unroll
            for (int i = 0; i < 10; i++)
                o[i] = acc[i] + pr[i] + fc_b[i];
        }
    }
}

// ============================================================================
extern "C" void kernel_launch(void* const* d_in, const int* in_sizes, int n_in,
                              void* d_out, int out_size)
{
    const float* x    = (const float*)d_in[0];
    const float* W_ih = (const float*)d_in[1];
    const float* W_hh = (const float*)d_in[2];
    const float* b_ih = (const float*)d_in[3];
    const float* b_hh = (const float*)d_in[4];
    const float* w_t  = (const float*)d_in[5];
    const float* fc_W = (const float*)d_in[6];
    const float* fc_b = (const float*)d_in[7];
    float* out = (float*)d_out;

    const int smem = 146944;
    // Idempotent; also runs on the pre-capture correctness call.
    cudaFuncSetAttribute(lstm_fused, cudaFuncAttributeMaxDynamicSharedMemorySize, smem);

    lstm_fused<<<Bn, 1024, smem>>>(x, W_ih, W_hh, b_ih, b_hh, w_t, fc_W, fc_b, out);
}